// round 5
// baseline (speedup 1.0000x reference)
#include <cuda_runtime.h>
#include <cstdint>

#define MLEN  16
#define DDIM  128
#define LNUM  26
#define KP    13
#define BPB   32      // words per block
#define NTHR  128     // 4 warps; 4 threads per word
#define GRID  512
#define XSTR  132     // padded floats per X row
#define DSTR  36
#define ETSTR 14
#define NBUF  2

// ---- smem layout (float indices) ----
#define XS_F    (BPB * XSTR)                  // 4224 per buffer
#define XOFF(b) ((b) * XS_F)
#define BPOFF   (NBUF * XS_F)                 // 8448 : Bp = 1024 uint2 = 2048 floats
#define DOFF    (BPOFF + 2048)                // 10496: D 32*36 = 1152
#define ETOFF   (DOFF + BPB * DSTR)           // 11648: expT 728
#define TSOFF   (ETOFF + LNUM * ETSTR * 2)    // 12376: T 676
#define REDOFF  (TSOFF + LNUM * LNUM)         // 13052
#define FLGOFF  (REDOFF + 4)                  // 13056
#define SMEM_F  (FLGOFF + 4)
#define SMEM_BYTES (SMEM_F * 4)               // ~51 KB -> 4 blocks/SM

__device__ float g_partials[GRID];
__device__ unsigned int g_count;

// ---------------- helpers ----------------
static __device__ __forceinline__ unsigned long long pack2(float lo, float hi){
    unsigned long long r; asm("mov.b64 %0, {%1,%2};" : "=l"(r) : "f"(lo), "f"(hi)); return r;
}
static __device__ __forceinline__ void unpack2(unsigned long long v, float& lo, float& hi){
    asm("mov.b64 {%0,%1}, %2;" : "=f"(lo), "=f"(hi) : "l"(v));
}
static __device__ __forceinline__ void ffma2(unsigned long long& d, unsigned long long a, unsigned long long b){
    asm("fma.rn.f32x2 %0, %1, %2, %0;" : "+l"(d) : "l"(a), "l"(b));
}
static __device__ __forceinline__ unsigned long long add2(unsigned long long a, unsigned long long b){
    unsigned long long r; asm("add.rn.f32x2 %0, %1, %2;" : "=l"(r) : "l"(a), "l"(b)); return r;
}
static __device__ __forceinline__ void cp16(uint32_t dst, const void* src){
    asm volatile("cp.async.cg.shared.global [%0], [%1], 16;" :: "r"(dst), "l"(src));
}
static __device__ __forceinline__ uint32_t bfpack(float lo, float hi){
    uint32_t r; asm("cvt.rn.bf16x2.f32 %0, %1, %2;" : "=r"(r) : "f"(hi), "f"(lo)); return r;
}
static __device__ __forceinline__ void mma_bf16(float* d, uint32_t a0, uint32_t a1, uint32_t a2, uint32_t a3,
                                                uint32_t b0, uint32_t b1){
    asm volatile("mma.sync.aligned.m16n8k16.row.col.f32.bf16.bf16.f32 "
                 "{%0,%1,%2,%3}, {%4,%5,%6,%7}, {%8,%9}, {%0,%1,%2,%3};"
                 : "+f"(d[0]), "+f"(d[1]), "+f"(d[2]), "+f"(d[3])
                 : "r"(a0), "r"(a1), "r"(a2), "r"(a3), "r"(b0), "r"(b1));
}

static __device__ __forceinline__ void stage_x(float* sm, const float4* X4, int b0, int s, int buf, int tid){
    uint32_t base = (uint32_t)__cvta_generic_to_shared(sm + XOFF(buf));
    #pragma unroll
    for (int u = 0; u < BPB * 32 / NTHR; u++) {        // 8 per thread
        int v = tid + u * NTHR;
        int i = v >> 5, f = v & 31;
        uint32_t dst = base + (uint32_t)(i * XSTR + f * 4) * 4u;
        cp16(dst, X4 + ((size_t)(b0 + i) * MLEN + s) * 32 + f);
    }
    asm volatile("cp.async.commit_group;" ::: "memory");
}

__global__ __launch_bounds__(NTHR, 4)
void crf_main(const float* __restrict__ X, const void* __restrict__ Yv,
              const float* __restrict__ W, const float* __restrict__ T,
              float* __restrict__ out)
{
    extern __shared__ float sm[];
    const int tid  = threadIdx.x;
    const int wid  = tid >> 5;
    const int lane = tid & 31;
    const int g    = lane >> 2, t = lane & 3;
    const int b0   = blockIdx.x * BPB;
    const float4* X4 = (const float4*)X;

    stage_x(sm, X4, b0, 0, 0, tid);
    stage_x(sm, X4, b0, 1, 1, tid);

    // ---- prepack bf16 B fragments ----
    uint2* Bp = (uint2*)(sm + BPOFF);
    #pragma unroll
    for (int u = 0; u < 8; u++) {
        int i = tid + u * NTHR;                        // 0..1023
        int kt = i >> 7, rem = i & 127, nt = rem >> 5, ln = rem & 31;
        int n  = nt * 8 + (ln >> 2);
        int k0 = kt * 16 + (ln & 3) * 2;
        float w0 = 0.f, w1 = 0.f, w2 = 0.f, w3 = 0.f;
        if (n < LNUM) {
            w0 = W[n * DDIM + k0];     w1 = W[n * DDIM + k0 + 1];
            w2 = W[n * DDIM + k0 + 8]; w3 = W[n * DDIM + k0 + 9];
        }
        Bp[i] = make_uint2(bfpack(w0, w1), bfpack(w2, w3));
    }
    float* ET  = sm + ETOFF;
    float* Tsm = sm + TSOFF;
    for (int i = tid; i < LNUM * ETSTR; i += NTHR) {
        int k = i / ETSTR, jp = i - k * ETSTR;
        float2 e = make_float2(0.f, 0.f);
        if (jp < KP) { e.x = __expf(T[k * LNUM + 2 * jp]); e.y = __expf(T[k * LNUM + 2 * jp + 1]); }
        ((float2*)ET)[i] = e;
    }
    for (int i = tid; i < LNUM * LNUM; i += NTHR) Tsm[i] = T[i];
    if (tid == 0) {
        const int* y32 = (const int*)Yv;
        int nz = 0;
        for (int i = 1; i < 128; i += 2) nz |= y32[i];
        ((int*)sm)[FLGOFF] = (nz == 0) ? 1 : 0;
    }
    __syncthreads();

    const bool is64 = ((int*)sm)[FLGOFF] != 0;
    const long long* Y64 = (const long long*)Yv;
    const int*       Y32 = (const int*)Yv;

    const int w = tid >> 2;          // word 0..31
    const int q = tid & 3;           // label-subset id
    const int b = b0 + w;

    int ycur = 0;
    if (q == 0) ycur = is64 ? (int)Y64[(size_t)b * MLEN] : Y32[(size_t)b * MLEN];

    float aq[7];
    #pragma unroll
    for (int i = 0; i < 7; i++) aq[i] = 1.0f;
    float node = 0.f, edge = 0.f, csc = 0.f, logz = 0.f;

    float* Dsm = sm + DOFF;
    const int rw = (wid & 1) * 16;       // GEMM row base for this warp
    const int nb = (wid >> 1) * 2;       // GEMM n-tile base (2 tiles of 8)

    for (int s = 0; s < MLEN; s++) {
        const int buf = s & 1;

        if (s < MLEN - 1) asm volatile("cp.async.wait_group 1;" ::: "memory");
        else              asm volatile("cp.async.wait_group 0;" ::: "memory");
        __syncthreads();

        // ---- GEMM: warp computes rows [rw,rw+16) x cols [nb*8,(nb+2)*8), K=128 ----
        {
            float acc[2][4];
            #pragma unroll
            for (int nt = 0; nt < 2; nt++)
                #pragma unroll
                for (int r = 0; r < 4; r++) acc[nt][r] = 0.f;

            const float* Xb = sm + XOFF(buf) + rw * XSTR;
            #pragma unroll
            for (int kt = 0; kt < 8; kt++) {
                const float* xp = Xb + g * XSTR + kt * 16 + t * 2;
                float2 v0 = *(const float2*)(xp);
                float2 v2 = *(const float2*)(xp + 8);
                float2 v1 = *(const float2*)(xp + 8 * XSTR);
                float2 v3 = *(const float2*)(xp + 8 * XSTR + 8);
                uint32_t a0 = bfpack(v0.x, v0.y);
                uint32_t a1 = bfpack(v1.x, v1.y);
                uint32_t a2 = bfpack(v2.x, v2.y);
                uint32_t a3 = bfpack(v3.x, v3.y);
                const uint2* bp = Bp + (kt * 4) * 32 + lane;
                uint2 bf0 = bp[nb * 32];
                uint2 bf1 = bp[(nb + 1) * 32];
                mma_bf16(acc[0], a0, a1, a2, a3, bf0.x, bf0.y);
                mma_bf16(acc[1], a0, a1, a2, a3, bf1.x, bf1.y);
            }
            int r0 = rw + g;
            #pragma unroll
            for (int nt = 0; nt < 2; nt++) {
                int c = (nb + nt) * 8 + t * 2;
                *(float2*)&Dsm[r0 * DSTR + c]       = make_float2(acc[nt][0], acc[nt][1]);
                *(float2*)&Dsm[(r0 + 8) * DSTR + c] = make_float2(acc[nt][2], acc[nt][3]);
            }
        }
        __syncthreads();

        if (s + 2 < MLEN) stage_x(sm, X4, b0, s + 2, buf, tid);

        // ---- recurrence: 4 threads per word, label subset k = q + 4i ----
        float ef_q[7];
        #pragma unroll
        for (int i = 0; i < 7; i++) {
            int k = q + 4 * i;
            ef_q[i] = (k < LNUM) ? Dsm[w * DSTR + k] : 0.f;
        }
        if (q == 0) node += Dsm[w * DSTR + ycur];

        if (s + 1 < MLEN) {
            int ynext = 0;
            if (q == 0) {
                ynext = is64 ? (int)Y64[(size_t)b * MLEN + s + 1] : Y32[(size_t)b * MLEN + s + 1];
                edge += Tsm[ycur * LNUM + ynext];
                ycur = ynext;
            }

            unsigned long long s2[KP];
            #pragma unroll
            for (int kp = 0; kp < KP; kp++) s2[kp] = 0ull;
            const ulonglong2* ETp = (const ulonglong2*)ET;
            #pragma unroll
            for (int i = 0; i < 7; i++) {
                int k = q + 4 * i;
                if (k < LNUM) {
                    float e  = __expf(ef_q[i]);
                    float bk = (s == 0) ? e : aq[i] * e;
                    unsigned long long bd = pack2(bk, bk);
                    const ulonglong2* er = ETp + k * (ETSTR / 2);
                    #pragma unroll
                    for (int j2 = 0; j2 < 7; j2++) {
                        ulonglong2 e2 = er[j2];
                        ffma2(s2[2 * j2], bd, e2.x);
                        if (2 * j2 + 1 < KP) ffma2(s2[2 * j2 + 1], bd, e2.y);
                    }
                }
            }
            // butterfly combine across the quad
            #pragma unroll
            for (int kp = 0; kp < KP; kp++)
                s2[kp] = add2(s2[kp], __shfl_xor_sync(0xffffffffu, s2[kp], 1));
            #pragma unroll
            for (int kp = 0; kp < KP; kp++)
                s2[kp] = add2(s2[kp], __shfl_xor_sync(0xffffffffu, s2[kp], 2));

            float sv[LNUM];
            #pragma unroll
            for (int kp = 0; kp < KP; kp++) unpack2(s2[kp], sv[2 * kp], sv[2 * kp + 1]);
            float m = sv[0];
            #pragma unroll
            for (int k = 1; k < LNUM; k++) m = fmaxf(m, sv[k]);
            float inv = __fdividef(1.0f, m);
            #pragma unroll
            for (int i = 0; i < 7; i++) {
                int k = q + 4 * i;
                if (k < LNUM) aq[i] = sv[k] * inv;
            }
            csc += __logf(m);
        } else {
            float ss = 0.f;
            #pragma unroll
            for (int i = 0; i < 7; i++) {
                int k = q + 4 * i;
                if (k < LNUM) ss += aq[i] * __expf(ef_q[i]);
            }
            ss += __shfl_xor_sync(0xffffffffu, ss, 1);
            ss += __shfl_xor_sync(0xffffffffu, ss, 2);
            if (q == 0) logz = csc + __logf(ss);
        }
    }

    // ---- block reduction (q==0 threads hold per-word values) ----
    float val = (q == 0) ? (logz - node - edge) : 0.f;
    #pragma unroll
    for (int o = 16; o; o >>= 1) val += __shfl_xor_sync(0xffffffffu, val, o);
    float* red = sm + REDOFF;
    if (lane == 0) red[wid] = val;
    __syncthreads();

    // ---- deterministic last-block global reduction ----
    __shared__ int s_last;
    if (tid == 0) {
        g_partials[blockIdx.x] = red[0] + red[1] + red[2] + red[3];
        __threadfence();
        unsigned int old = atomicAdd(&g_count, 1u);
        s_last = (old == (unsigned)(gridDim.x - 1)) ? 1 : 0;
    }
    __syncthreads();
    if (s_last && tid < 32) {
        __threadfence();
        const volatile float* gp = (const volatile float*)g_partials;
        float v = 0.f;
        #pragma unroll
        for (int i = 0; i < GRID / 32; i++) v += gp[lane + i * 32];  // fixed order
        #pragma unroll
        for (int o = 16; o; o >>= 1) v += __shfl_xor_sync(0xffffffffu, v, o);
        if (lane == 0) { out[0] = v; g_count = 0; }
    }
}

extern "C" void kernel_launch(void* const* d_in, const int* in_sizes, int n_in,
                              void* d_out, int out_size)
{
    const float* X = (const float*)d_in[0];
    const void*  Y = d_in[1];
    const float* W = (const float*)d_in[2];
    const float* T = (const float*)d_in[3];

    cudaFuncSetAttribute(crf_main, cudaFuncAttributeMaxDynamicSharedMemorySize, SMEM_BYTES);
    crf_main<<<GRID, NTHR, SMEM_BYTES>>>(X, Y, W, T, (float*)d_out);
}

// round 6
// speedup vs baseline: 1.3886x; 1.3886x over previous
#include <cuda_runtime.h>
#include <cstdint>

#define MLEN  16
#define DDIM  128
#define LNUM  26
#define KP    13
#define BPB   64      // words per block = 4 warps x 16
#define NTHR  128
#define GRID  256
#define DSTR  34      // lanes 0-15 stride 34 -> conflict-free scalar/64b LDS
#define ETSTR 14
#define R8    (8 * MLEN * DDIM)   // float offset between row g and g+8

__device__ float g_partials[GRID];
__device__ unsigned int g_count;

__shared__ uint2 Bp_s[1024];                 // bf16 B fragments, 8KB
__shared__ float Dsm_s[BPB * DSTR];          // emissions exchange, 8.7KB
__shared__ float ET_s[LNUM * ETSTR * 2];     // expT packed j-pairs
__shared__ float Tsm_s[LNUM * LNUM];
__shared__ float red_s[4];
__shared__ int   flag_s;

// ---------------- helpers ----------------
static __device__ __forceinline__ unsigned long long pack2(float lo, float hi){
    unsigned long long r; asm("mov.b64 %0, {%1,%2};" : "=l"(r) : "f"(lo), "f"(hi)); return r;
}
static __device__ __forceinline__ void unpack2(unsigned long long v, float& lo, float& hi){
    asm("mov.b64 {%0,%1}, %2;" : "=f"(lo), "=f"(hi) : "l"(v));
}
static __device__ __forceinline__ void ffma2(unsigned long long& d, unsigned long long a, unsigned long long b){
    asm("fma.rn.f32x2 %0, %1, %2, %0;" : "+l"(d) : "l"(a), "l"(b));
}
static __device__ __forceinline__ uint32_t bfpack(float lo, float hi){
    uint32_t r; asm("cvt.rn.bf16x2.f32 %0, %1, %2;" : "=r"(r) : "f"(hi), "f"(lo)); return r;
}
static __device__ __forceinline__ void mma_bf16(float* d, uint32_t a0, uint32_t a1, uint32_t a2, uint32_t a3,
                                                uint32_t b0, uint32_t b1){
    asm volatile("mma.sync.aligned.m16n8k16.row.col.f32.bf16.bf16.f32 "
                 "{%0,%1,%2,%3}, {%4,%5,%6,%7}, {%8,%9}, {%0,%1,%2,%3};"
                 : "+f"(d[0]), "+f"(d[1]), "+f"(d[2]), "+f"(d[3])
                 : "r"(a0), "r"(a1), "r"(a2), "r"(a3), "r"(b0), "r"(b1));
}

__global__ __launch_bounds__(NTHR, 2)
void crf_main(const float* __restrict__ X, const void* __restrict__ Yv,
              const float* __restrict__ W, const float* __restrict__ T,
              float* __restrict__ out)
{
    const int tid  = threadIdx.x;
    const int wid  = tid >> 5;
    const int lane = tid & 31;
    const int g    = lane >> 2, t = lane & 3;
    const int b0   = blockIdx.x * BPB;

    // ---- init: prepack bf16 B fragments (identical layout to R4, proven) ----
    #pragma unroll
    for (int u = 0; u < 8; u++) {
        int i = tid + u * NTHR;
        int kt = i >> 7, rem = i & 127, nt = rem >> 5, ln = rem & 31;
        int n  = nt * 8 + (ln >> 2);
        int k0 = kt * 16 + (ln & 3) * 2;
        float w0 = 0.f, w1 = 0.f, w2 = 0.f, w3 = 0.f;
        if (n < LNUM) {
            w0 = W[n * DDIM + k0];     w1 = W[n * DDIM + k0 + 1];
            w2 = W[n * DDIM + k0 + 8]; w3 = W[n * DDIM + k0 + 9];
        }
        Bp_s[i] = make_uint2(bfpack(w0, w1), bfpack(w2, w3));
    }
    for (int i = tid; i < LNUM * ETSTR; i += NTHR) {
        int k = i / ETSTR, jp = i - k * ETSTR;
        float2 e = make_float2(0.f, 0.f);
        if (jp < KP) { e.x = __expf(T[k * LNUM + 2 * jp]); e.y = __expf(T[k * LNUM + 2 * jp + 1]); }
        ((float2*)ET_s)[i] = e;
    }
    for (int i = tid; i < LNUM * LNUM; i += NTHR) Tsm_s[i] = T[i];
    if (tid == 0) {
        const int* y32 = (const int*)Yv;
        int nz = 0;
        for (int i = 1; i < 128; i += 2) nz |= y32[i];
        flag_s = (nz == 0) ? 1 : 0;
    }
    __syncthreads();

    const bool is64 = flag_s != 0;
    const long long* Y64 = (const long long*)Yv;
    const int*       Y32 = (const int*)Yv;

    // warp wid: GEMM rows [wid*16, wid*16+16), recurrence words wid*16+lane (lane<16)
    const int rw = wid * 16;
    const int w  = rw + (lane & 15);          // word this lane recurs over (lane<16)
    const int b  = b0 + w;
    const bool owner = (lane < 16);

    int ycur = 0;
    if (owner) ycur = is64 ? (int)Y64[(size_t)b * MLEN] : Y32[(size_t)b * MLEN];

    float a[LNUM];
    #pragma unroll
    for (int k = 0; k < LNUM; k++) a[k] = 1.0f;
    float node = 0.f, edge = 0.f, csc = 0.f, logz = 0.f;

    // A-fragment base for this thread (rows rw+g and rw+g+8)
    const float* xbase = X + ((size_t)(b0 + rw + g) * MLEN) * DDIM + t * 2;

    for (int s = 0; s < MLEN; s++) {
        // ---- load + convert all A fragments for this position (MLP ~32) ----
        const float* xp = xbase + s * DDIM;
        uint32_t A[8][4];
        #pragma unroll
        for (int kt = 0; kt < 8; kt++) {
            float2 v0 = *(const float2*)(xp + kt * 16);
            float2 v2 = *(const float2*)(xp + kt * 16 + 8);
            float2 v1 = *(const float2*)(xp + kt * 16 + R8);
            float2 v3 = *(const float2*)(xp + kt * 16 + R8 + 8);
            A[kt][0] = bfpack(v0.x, v0.y);
            A[kt][1] = bfpack(v1.x, v1.y);
            A[kt][2] = bfpack(v2.x, v2.y);
            A[kt][3] = bfpack(v3.x, v3.y);
        }

        // ---- GEMM: 16 rows x 32 cols, K=128 ----
        float acc[4][4];
        #pragma unroll
        for (int nt = 0; nt < 4; nt++)
            #pragma unroll
            for (int r = 0; r < 4; r++) acc[nt][r] = 0.f;

        #pragma unroll
        for (int kt = 0; kt < 8; kt++) {
            const uint2* bp = Bp_s + kt * 128 + lane;
            uint2 bf0 = bp[0];
            uint2 bf1 = bp[32];
            uint2 bf2 = bp[64];
            uint2 bf3 = bp[96];
            mma_bf16(acc[0], A[kt][0], A[kt][1], A[kt][2], A[kt][3], bf0.x, bf0.y);
            mma_bf16(acc[1], A[kt][0], A[kt][1], A[kt][2], A[kt][3], bf1.x, bf1.y);
            mma_bf16(acc[2], A[kt][0], A[kt][1], A[kt][2], A[kt][3], bf2.x, bf2.y);
            mma_bf16(acc[3], A[kt][0], A[kt][1], A[kt][2], A[kt][3], bf3.x, bf3.y);
        }
        {
            int r0 = rw + g;
            #pragma unroll
            for (int nt = 0; nt < 4; nt++) {
                int c = nt * 8 + t * 2;
                *(float2*)&Dsm_s[r0 * DSTR + c]       = make_float2(acc[nt][0], acc[nt][1]);
                *(float2*)&Dsm_s[(r0 + 8) * DSTR + c] = make_float2(acc[nt][2], acc[nt][3]);
            }
        }
        __syncwarp();   // D rows of this warp visible to this warp's lanes

        // ---- recurrence: lanes 0-15, one word each ----
        if (owner) {
            float ef[LNUM];
            const float2* dr = (const float2*)&Dsm_s[w * DSTR];
            #pragma unroll
            for (int p = 0; p < KP; p++) {
                float2 v = dr[p];
                ef[2 * p] = v.x; ef[2 * p + 1] = v.y;
            }

            #pragma unroll
            for (int k = 0; k < LNUM; k++) if (ycur == k) node += ef[k];

            if (s + 1 < MLEN) {
                int ynext = is64 ? (int)Y64[(size_t)b * MLEN + s + 1] : Y32[(size_t)b * MLEN + s + 1];
                edge += Tsm_s[ycur * LNUM + ynext];

                unsigned long long s2[KP];
                #pragma unroll
                for (int kp = 0; kp < KP; kp++) s2[kp] = 0ull;
                const ulonglong2* ETp = (const ulonglong2*)ET_s;
                #pragma unroll
                for (int k = 0; k < LNUM; k++) {
                    float e  = __expf(ef[k]);
                    float bk = (s == 0) ? e : a[k] * e;
                    unsigned long long bd = pack2(bk, bk);
                    const ulonglong2* er = ETp + k * (ETSTR / 2);
                    #pragma unroll
                    for (int j2 = 0; j2 < 7; j2++) {
                        ulonglong2 e2 = er[j2];
                        ffma2(s2[2 * j2], bd, e2.x);
                        if (2 * j2 + 1 < KP) ffma2(s2[2 * j2 + 1], bd, e2.y);
                    }
                }
                float sv[LNUM];
                #pragma unroll
                for (int kp = 0; kp < KP; kp++) unpack2(s2[kp], sv[2 * kp], sv[2 * kp + 1]);
                float m = sv[0];
                #pragma unroll
                for (int k = 1; k < LNUM; k++) m = fmaxf(m, sv[k]);
                float inv = __fdividef(1.0f, m);
                #pragma unroll
                for (int k = 0; k < LNUM; k++) a[k] = sv[k] * inv;
                csc += __logf(m);
                ycur = ynext;
            } else {
                float ssum = 0.f;
                #pragma unroll
                for (int k = 0; k < LNUM; k++) ssum += a[k] * __expf(ef[k]);
                logz = csc + __logf(ssum);
            }
        }
        __syncwarp();   // all lanes done reading D before next position's STS
    }

    // ---- reduction ----
    float val = owner ? (logz - node - edge) : 0.f;
    #pragma unroll
    for (int o = 16; o; o >>= 1) val += __shfl_xor_sync(0xffffffffu, val, o);
    if (lane == 0) red_s[wid] = val;
    __syncthreads();

    __shared__ int s_last;
    if (tid == 0) {
        g_partials[blockIdx.x] = red_s[0] + red_s[1] + red_s[2] + red_s[3];
        __threadfence();
        unsigned int old = atomicAdd(&g_count, 1u);
        s_last = (old == (unsigned)(gridDim.x - 1)) ? 1 : 0;
    }
    __syncthreads();
    if (s_last && tid < 32) {
        __threadfence();
        const volatile float* gp = (const volatile float*)g_partials;
        float v = 0.f;
        #pragma unroll
        for (int i = 0; i < GRID / 32; i++) v += gp[lane + i * 32];  // fixed order
        #pragma unroll
        for (int o = 16; o; o >>= 1) v += __shfl_xor_sync(0xffffffffu, v, o);
        if (lane == 0) { out[0] = v; g_count = 0; }
    }
}

extern "C" void kernel_launch(void* const* d_in, const int* in_sizes, int n_in,
                              void* d_out, int out_size)
{
    const float* X = (const float*)d_in[0];
    const void*  Y = d_in[1];
    const float* W = (const float*)d_in[2];
    const float* T = (const float*)d_in[3];

    crf_main<<<GRID, NTHR>>>(X, Y, W, T, (float*)d_out);
}